// round 1
// baseline (speedup 1.0000x reference)
#include <cuda_runtime.h>
#include <math.h>

// NT_Xent collapsed: neg_n = (r_n/||r_n||) . S / T, S = sum_m mem_m/||mem_m||.
// K1: stream 32MB memory bank -> per-block partial S (deterministic tree sum).
// K2: reduce partials, per-row pos/neg + log_softmax loss -> per-block partial loss.
// K3: mean -> d_out[0].

#define D      128
#define DV     32            // float4 per row
#define B1     148
#define T1     512
#define NW1    (T1 / 32)     // warps per block in K1
#define B2     32
#define T2     256
#define NW2    (T2 / 32)
#define INV_T  10.0f         // 1 / TEMPERATURE
#define EPSN   1e-8f

__device__ float g_partialS[B1 * D];
__device__ float g_partialLoss[B2];

__device__ __forceinline__ float warp_sum(float v) {
    #pragma unroll
    for (int o = 16; o > 0; o >>= 1) v += __shfl_xor_sync(0xffffffffu, v, o);
    return v;
}

// ---------------- K1: memory-bank reduction ----------------
__global__ __launch_bounds__(T1) void bank_reduce_kernel(const float4* __restrict__ mem, int M) {
    const int tid  = threadIdx.x;
    const int w    = tid >> 5;
    const int lane = tid & 31;
    const int gw   = blockIdx.x * NW1 + w;     // global warp id
    const int W    = B1 * NW1;                 // total warps

    float4 acc = make_float4(0.f, 0.f, 0.f, 0.f);

    const int iters = (M + W - 1) / W;         // rows per warp (ceil)
    for (int k = 0; k < iters; k += 4) {
        float4 v[4];
        #pragma unroll
        for (int u = 0; u < 4; u++) {
            int m = gw + (k + u) * W;
            v[u] = (m < M) ? mem[(size_t)m * DV + lane]
                           : make_float4(0.f, 0.f, 0.f, 0.f);
        }
        #pragma unroll
        for (int u = 0; u < 4; u++) {
            float s = v[u].x * v[u].x + v[u].y * v[u].y
                    + v[u].z * v[u].z + v[u].w * v[u].w;
            s = warp_sum(s);
            float inv = 1.0f / fmaxf(sqrtf(s), EPSN);  // zero rows contribute 0
            acc.x += v[u].x * inv;
            acc.y += v[u].y * inv;
            acc.z += v[u].z * inv;
            acc.w += v[u].w * inv;
        }
    }

    __shared__ float4 sacc[NW1][32];
    sacc[w][lane] = acc;
    __syncthreads();

    if (tid < D) {
        float s = 0.f;
        #pragma unroll
        for (int ww = 0; ww < NW1; ww++)
            s += ((const float*)sacc[ww])[tid];
        g_partialS[blockIdx.x * D + tid] = s;
    }
}

// ---------------- K2: per-sample loss ----------------
__global__ __launch_bounds__(T2) void loss_kernel(const float4* __restrict__ real,
                                                  const float4* __restrict__ pert,
                                                  int N) {
    __shared__ float S[D];
    __shared__ float wsum[NW2];

    const int tid  = threadIdx.x;
    const int w    = tid >> 5;
    const int lane = tid & 31;

    if (tid < D) {
        float s = 0.f;
        #pragma unroll 4
        for (int b = 0; b < B1; b++)
            s += g_partialS[b * D + tid];
        S[tid] = s;
    }
    __syncthreads();

    const float4 s4 = ((const float4*)S)[lane];

    const int rowsPerBlock = (N + B2 - 1) / B2;
    const int rowsPerWarp  = (rowsPerBlock + NW2 - 1) / NW2;

    float lsum = 0.f;
    for (int r = 0; r < rowsPerWarp; r++) {
        int n = blockIdx.x * rowsPerBlock + w * rowsPerWarp + r;
        if (n < N) {
            float4 rv = real[(size_t)n * DV + lane];
            float4 pv = pert[(size_t)n * DV + lane];
            float rr = rv.x*rv.x + rv.y*rv.y + rv.z*rv.z + rv.w*rv.w;
            float pp = pv.x*pv.x + pv.y*pv.y + pv.z*pv.z + pv.w*pv.w;
            float rp = rv.x*pv.x + rv.y*pv.y + rv.z*pv.z + rv.w*pv.w;
            float rs = rv.x*s4.x + rv.y*s4.y + rv.z*s4.z + rv.w*s4.w;
            rr = warp_sum(rr);
            pp = warp_sum(pp);
            rp = warp_sum(rp);
            rs = warp_sum(rs);
            if (lane == 0) {
                float rn  = fmaxf(sqrtf(rr), EPSN);
                float pn  = fmaxf(sqrtf(pp), EPSN);
                float pos = rp / (rn * pn) * INV_T;
                float neg = rs / rn * INV_T;
                float mx  = fmaxf(pos, neg);
                float lse = mx + logf(expf(pos - mx) + expf(neg - mx));
                lsum += lse - pos;   // = -log_softmax[0]
            }
        }
    }

    if (lane == 0) wsum[w] = lsum;
    __syncthreads();
    if (tid == 0) {
        float b = 0.f;
        #pragma unroll
        for (int ww = 0; ww < NW2; ww++) b += wsum[ww];
        g_partialLoss[blockIdx.x] = b;
    }
}

// ---------------- K3: final mean ----------------
__global__ void finalize_kernel(float* __restrict__ out, int N) {
    int lane = threadIdx.x;
    float v = (lane < B2) ? g_partialLoss[lane] : 0.f;
    v = warp_sum(v);
    if (lane == 0) out[0] = v / (float)N;
}

extern "C" void kernel_launch(void* const* d_in, const int* in_sizes, int n_in,
                              void* d_out, int out_size) {
    const float4* real = (const float4*)d_in[0];
    const float4* pert = (const float4*)d_in[1];
    const float4* mem  = (const float4*)d_in[2];
    int N = in_sizes[0] / D;
    int M = in_sizes[2] / D;

    bank_reduce_kernel<<<B1, T1>>>(mem, M);
    loss_kernel<<<B2, T2>>>(real, pert, N);
    finalize_kernel<<<1, 32>>>((float*)d_out, N);
}

// round 2
// speedup vs baseline: 1.1843x; 1.1843x over previous
#include <cuda_runtime.h>
#include <math.h>

// NT_Xent collapsed: neg_n = (r_n/||r_n||) . S / T,  S = sum_m mem_m/||mem_m||.
// Single persistent kernel, grid = 148 (one 1024-thread block per SM, all resident):
//   Phase 1: all blocks stream the 32MB bank -> g_partialS[block][128]
//   grid-sync (threadfence + atomic counter)
//   Phase 2: first 16 blocks reduce S, compute per-row loss -> g_partialLoss
//   last-done block sums losses, writes mean, resets counters (graph-replay safe).
// All float reductions are fixed-order trees -> deterministic output.

#define D       128
#define DV      32           // float4 per row
#define GRID    148
#define T       1024
#define NW      (T / 32)     // 32 warps per block
#define LOSSB   16           // blocks participating in phase 2
#define INV_T   10.0f        // 1 / TEMPERATURE
#define EPSN    1e-8f

__device__ float    g_partialS[GRID * D];
__device__ float    g_partialLoss[LOSSB];
__device__ unsigned g_cnt1 = 0;
__device__ unsigned g_cnt2 = 0;

__device__ __forceinline__ float warp_sum(float v) {
    #pragma unroll
    for (int o = 16; o > 0; o >>= 1) v += __shfl_xor_sync(0xffffffffu, v, o);
    return v;
}

__global__ __launch_bounds__(T, 1)
void fused_ntxent_kernel(const float4* __restrict__ mem, int M,
                         const float4* __restrict__ real,
                         const float4* __restrict__ pert, int N,
                         float* __restrict__ out) {
    const int tid  = threadIdx.x;
    const int w    = tid >> 5;
    const int lane = tid & 31;
    const int bid  = blockIdx.x;
    const int gw   = bid * NW + w;       // global warp id
    const int W    = GRID * NW;          // 4736 warps total

    __shared__ float4 sacc[NW][32];      // 16 KB
    __shared__ float  Sq[8][D];          // 4 KB
    __shared__ float  S[D];
    __shared__ float  wsum[NW];

    // ---------------- Phase 1: memory-bank reduction ----------------
    float4 acc = make_float4(0.f, 0.f, 0.f, 0.f);
    const int iters = (M + W - 1) / W;
    for (int k = 0; k < iters; k += 4) {
        float4 v[4];
        #pragma unroll
        for (int u = 0; u < 4; u++) {
            int m = gw + (k + u) * W;
            v[u] = (m < M) ? mem[(size_t)m * DV + lane]
                           : make_float4(0.f, 0.f, 0.f, 0.f);
        }
        #pragma unroll
        for (int u = 0; u < 4; u++) {
            float s = v[u].x * v[u].x + v[u].y * v[u].y
                    + v[u].z * v[u].z + v[u].w * v[u].w;
            s = warp_sum(s);
            float inv = 1.0f / fmaxf(sqrtf(s), EPSN);  // all-zero row -> 0 contribution
            acc.x += v[u].x * inv;
            acc.y += v[u].y * inv;
            acc.z += v[u].z * inv;
            acc.w += v[u].w * inv;
        }
    }

    sacc[w][lane] = acc;
    __syncthreads();

    if (tid < D) {
        float s = 0.f;
        #pragma unroll
        for (int ww = 0; ww < NW; ww++)
            s += ((const float*)sacc[ww])[tid];
        g_partialS[bid * D + tid] = s;
    }
    __threadfence();
    __syncthreads();
    if (tid == 0) atomicAdd(&g_cnt1, 1u);

    if (bid >= LOSSB) return;

    // ---------------- grid sync ----------------
    if (tid == 0) {
        while (*((volatile unsigned*)&g_cnt1) != GRID) { }
        __threadfence();
    }
    __syncthreads();

    // ---------------- Phase 2a: reduce S (fixed order per column) ----------------
    {
        const int col = tid & (D - 1);
        const int q   = tid >> 7;            // 0..7
        float s = 0.f;
        for (int b = q; b < GRID; b += 8)
            s += g_partialS[b * D + col];
        Sq[q][col] = s;
    }
    __syncthreads();
    if (tid < D) {
        float t = 0.f;
        #pragma unroll
        for (int j = 0; j < 8; j++) t += Sq[j][tid];
        S[tid] = t;
    }
    __syncthreads();

    const float4 s4 = ((const float4*)S)[lane];

    // ---------------- Phase 2b: per-row loss (warp per row) ----------------
    float lsum = 0.f;
    for (int n = bid * NW + w; n < N; n += LOSSB * NW) {
        float4 rv = real[(size_t)n * DV + lane];
        float4 pv = pert[(size_t)n * DV + lane];
        float rr = rv.x*rv.x + rv.y*rv.y + rv.z*rv.z + rv.w*rv.w;
        float pp = pv.x*pv.x + pv.y*pv.y + pv.z*pv.z + pv.w*pv.w;
        float rp = rv.x*pv.x + rv.y*pv.y + rv.z*pv.z + rv.w*pv.w;
        float rs = rv.x*s4.x + rv.y*s4.y + rv.z*s4.z + rv.w*s4.w;
        rr = warp_sum(rr);
        pp = warp_sum(pp);
        rp = warp_sum(rp);
        rs = warp_sum(rs);
        if (lane == 0) {
            float rn  = fmaxf(sqrtf(rr), EPSN);
            float pn  = fmaxf(sqrtf(pp), EPSN);
            float pos = rp / (rn * pn) * INV_T;
            float neg = rs / rn * INV_T;
            float mx  = fmaxf(pos, neg);
            float lse = mx + logf(expf(pos - mx) + expf(neg - mx));
            lsum += lse - pos;               // -log_softmax[0]
        }
    }

    if (lane == 0) wsum[w] = lsum;
    __syncthreads();

    if (tid == 0) {
        float b = 0.f;
        #pragma unroll
        for (int ww = 0; ww < NW; ww++) b += wsum[ww];
        g_partialLoss[bid] = b;
        __threadfence();
        unsigned ret = atomicAdd(&g_cnt2, 1u);
        if (ret == LOSSB - 1) {
            // last phase-2 block: final reduce + reset counters for next replay
            __threadfence();
            float t = 0.f;
            #pragma unroll
            for (int i = 0; i < LOSSB; i++) t += g_partialLoss[i];
            out[0] = t / (float)N;
            g_cnt1 = 0;
            g_cnt2 = 0;
        }
    }
}

extern "C" void kernel_launch(void* const* d_in, const int* in_sizes, int n_in,
                              void* d_out, int out_size) {
    const float4* real = (const float4*)d_in[0];
    const float4* pert = (const float4*)d_in[1];
    const float4* mem  = (const float4*)d_in[2];
    int N = in_sizes[0] / D;
    int M = in_sizes[2] / D;

    fused_ntxent_kernel<<<GRID, T>>>(mem, M, real, pert, N, (float*)d_out);
}

// round 3
// speedup vs baseline: 1.4877x; 1.2562x over previous
#include <cuda_runtime.h>
#include <math.h>

// NT_Xent collapsed: neg_n = (r_n/||r_n||) . S / T,  S = sum_m mem_m/||mem_m||.
// One persistent kernel, grid = 148 x 1024 (all blocks co-resident):
//   Phase 1: stream 32MB bank with 8-deep MLP batches -> g_partialS[148][128]
//   grid-sync; Phase 2: every block rebuilds S, 7 warps/block do loss rows;
//   last-arriving block reduces 148 partial losses -> mean -> out.
// All reductions are fixed-order trees -> deterministic.

#define D      128
#define DV     32            // float4 per row
#define GRID   148
#define T      1024
#define NW     32            // warps per block
#define INV_T  10.0f
#define EPSN   1e-8f
#define EPS2   (1e-8f * 1e-8f)

__device__ float    g_partialS[GRID * D];
__device__ float    g_partialLoss[GRID];
__device__ unsigned g_cnt1 = 0;
__device__ unsigned g_cnt2 = 0;

__device__ __forceinline__ float warp_sum(float v) {
    #pragma unroll
    for (int o = 16; o > 0; o >>= 1) v += __shfl_xor_sync(0xffffffffu, v, o);
    return v;
}

__device__ __forceinline__ float dot4(float4 a, float4 b) {
    return a.x * b.x + a.y * b.y + a.z * b.z + a.w * b.w;
}

__global__ __launch_bounds__(T, 1)
void fused_ntxent_kernel(const float4* __restrict__ mem, int M,
                         const float4* __restrict__ real,
                         const float4* __restrict__ pert, int N,
                         float* __restrict__ out) {
    const int tid  = threadIdx.x;
    const int w    = tid >> 5;
    const int lane = tid & 31;
    const int bid  = blockIdx.x;
    const int gw   = bid * NW + w;          // global warp id
    const int W    = GRID * NW;             // 4736 warps

    __shared__ float4 sacc[NW][32];         // 16 KB
    __shared__ float  Sq[8][D];             // 4 KB
    __shared__ float  S[D];
    __shared__ float  wsum[NW];
    __shared__ int    islast;

    // ================= Phase 1: memory-bank reduction =================
    float4 acc = make_float4(0.f, 0.f, 0.f, 0.f);
    const int full = M / W;                 // rows fully covered by every warp
    const int rem  = M - full * W;
    const float4* base = mem + (size_t)gw * DV + lane;
    const size_t  step = (size_t)W * DV;    // float4 stride per k

    int k = 0;
    // 8-deep batches: 8 independent LDG.128 in flight per warp
    #pragma unroll 1
    for (; k + 8 <= full; k += 8) {
        float4 v[8];
        #pragma unroll
        for (int u = 0; u < 8; u++) v[u] = base[(size_t)(k + u) * step];
        float s[8];
        #pragma unroll
        for (int u = 0; u < 8; u++) s[u] = dot4(v[u], v[u]);
        #pragma unroll
        for (int o = 16; o > 0; o >>= 1) {
            #pragma unroll
            for (int u = 0; u < 8; u++) s[u] += __shfl_xor_sync(0xffffffffu, s[u], o);
        }
        #pragma unroll
        for (int u = 0; u < 8; u++) {
            float inv = rsqrtf(fmaxf(s[u], EPS2));   // == 1/max(sqrt(s),EPS)
            acc.x += v[u].x * inv;  acc.y += v[u].y * inv;
            acc.z += v[u].z * inv;  acc.w += v[u].w * inv;
        }
    }
    // 4-deep tail batch
    #pragma unroll 1
    for (; k + 4 <= full; k += 4) {
        float4 v[4];
        #pragma unroll
        for (int u = 0; u < 4; u++) v[u] = base[(size_t)(k + u) * step];
        float s[4];
        #pragma unroll
        for (int u = 0; u < 4; u++) s[u] = dot4(v[u], v[u]);
        #pragma unroll
        for (int o = 16; o > 0; o >>= 1) {
            #pragma unroll
            for (int u = 0; u < 4; u++) s[u] += __shfl_xor_sync(0xffffffffu, s[u], o);
        }
        #pragma unroll
        for (int u = 0; u < 4; u++) {
            float inv = rsqrtf(fmaxf(s[u], EPS2));
            acc.x += v[u].x * inv;  acc.y += v[u].y * inv;
            acc.z += v[u].z * inv;  acc.w += v[u].w * inv;
        }
    }
    // scalar tail + remainder row
    #pragma unroll 1
    for (; k <= full; k++) {
        if (k == full && gw >= rem) break;
        float4 v = base[(size_t)k * step];
        float s = warp_sum(dot4(v, v));
        float inv = rsqrtf(fmaxf(s, EPS2));
        acc.x += v.x * inv;  acc.y += v.y * inv;
        acc.z += v.z * inv;  acc.w += v.w * inv;
    }

    sacc[w][lane] = acc;
    __syncthreads();
    if (tid < D) {
        float s = 0.f;
        #pragma unroll
        for (int ww = 0; ww < NW; ww++)
            s += ((const float*)sacc[ww])[tid];
        g_partialS[bid * D + tid] = s;
    }
    __threadfence();
    __syncthreads();
    if (tid == 0) atomicAdd(&g_cnt1, 1u);

    // ================= grid sync =================
    if (tid == 0) {
        while (*((volatile unsigned*)&g_cnt1) != GRID) { }
        __threadfence();
    }
    __syncthreads();

    // ================= Phase 2a: rebuild S (parallel, fixed order) =================
    {
        const int col = tid & (D - 1);
        const int q   = tid >> 7;           // 0..7
        float s = 0.f;
        #pragma unroll 1
        for (int b = q; b < GRID; b += 8)
            s += g_partialS[b * D + col];
        Sq[q][col] = s;
    }
    __syncthreads();
    if (tid < D) {
        float t = 0.f;
        #pragma unroll
        for (int j = 0; j < 8; j++) t += Sq[j][tid];
        S[tid] = t;
    }
    __syncthreads();

    const float4 s4 = ((const float4*)S)[lane];

    // ================= Phase 2b: per-row loss, spread over all blocks =================
    float lsum = 0.f;
    {
        int n = w * GRID + bid;             // warps 0..6 get valid rows (N=1024)
        if (n < N) {
            float4 rv = real[(size_t)n * DV + lane];
            float4 pv = pert[(size_t)n * DV + lane];
            float rr = warp_sum(dot4(rv, rv));
            float pp = warp_sum(dot4(pv, pv));
            float rp = warp_sum(dot4(rv, pv));
            float rs = warp_sum(dot4(rv, s4));
            if (lane == 0) {
                float rn  = fmaxf(sqrtf(rr), EPSN);
                float pn  = fmaxf(sqrtf(pp), EPSN);
                float pos = rp / (rn * pn) * INV_T;
                float neg = rs / rn * INV_T;
                float mx  = fmaxf(pos, neg);
                float lse = mx + logf(expf(pos - mx) + expf(neg - mx));
                lsum = lse - pos;           // -log_softmax[0]
            }
        }
    }
    if (lane == 0) wsum[w] = lsum;
    __syncthreads();

    if (tid == 0) {
        float b = 0.f;
        #pragma unroll
        for (int ww = 0; ww < NW; ww++) b += wsum[ww];
        g_partialLoss[bid] = b;
        __threadfence();
        unsigned ret = atomicAdd(&g_cnt2, 1u);
        islast = (ret == GRID - 1) ? 1 : 0;
    }
    __syncthreads();

    // last-arriving block: final loss reduce + reset counters for graph replay
    if (islast && w == 0) {
        __threadfence();
        float v = 0.f;
        #pragma unroll
        for (int j = 0; j < 5; j++) {
            int i = lane + 32 * j;
            if (i < GRID) v += g_partialLoss[i];
        }
        v = warp_sum(v);
        if (lane == 0) {
            out[0] = v / (float)N;
            g_cnt1 = 0;
            g_cnt2 = 0;
        }
    }
}

extern "C" void kernel_launch(void* const* d_in, const int* in_sizes, int n_in,
                              void* d_out, int out_size) {
    const float4* real = (const float4*)d_in[0];
    const float4* pert = (const float4*)d_in[1];
    const float4* mem  = (const float4*)d_in[2];
    int N = in_sizes[0] / D;
    int M = in_sizes[2] / D;

    fused_ntxent_kernel<<<GRID, T>>>(mem, M, real, pert, N, (float*)d_out);
}